// round 10
// baseline (speedup 1.0000x reference)
#include <cuda_runtime.h>
#include <cstdint>

#define N 8192
#define NW 128          // max 64-bit words per active mask row (N/64)
#define SCAN_SMEM_WORDS 20480   // 160 KB dynamic smem budget for staged mask
typedef unsigned long long u64;
typedef unsigned int u32;

// ---------------- device globals (zero-initialized at module load) ----------------
__device__ u32 g_maxbox;
__device__ int g_cnt;      // valid boxes (score > 0.25)
__device__ int g_cnt_a;    // active valid boxes (positive area)
__device__ float g_x1[N], g_y1[N], g_x2[N], g_y2[N], g_sc[N];
__device__ u64 g_keys[N];  // (~mono(score))<<32 | idx<<1 | act   -- full-u64 comparable
__device__ float g_sx1[N], g_sy1[N], g_sx2[N], g_sy2[N], g_ssc[N], g_sar[N]; // sorted actives
__device__ int g_apos[N];  // sorted-active rank -> overall sorted position (output row)
__device__ u64 g_mask[N * NW];   // suppression bitmask among actives

__device__ __forceinline__ u32 fmono(float f) {
    u32 u = __float_as_uint(f);
    return (u & 0x80000000u) ? ~u : (u | 0x80000000u);
}

// decode boxes, coord max, warp-aggregated compaction of valid keys, zero output
__global__ void k_prep(const float* __restrict__ p, float* __restrict__ out) {
    int i = blockIdx.x * blockDim.x + threadIdx.x;   // grid covers exactly N
    float cx = p[i], cy = p[N + i], pw = p[2*N + i], ph = p[3*N + i], s = p[4*N + i];
    float x1 = cx - pw*0.5f, y1 = cy - ph*0.5f, x2 = cx + pw*0.5f, y2 = cy + ph*0.5f;
    g_x1[i]=x1; g_y1[i]=y1; g_x2[i]=x2; g_y2[i]=y2; g_sc[i]=s;

    int lane = threadIdx.x & 31;
    u32 m = fmono(fmaxf(fmaxf(x1,x2), fmaxf(y1,y2)));
    #pragma unroll
    for (int o = 16; o; o >>= 1) m = max(m, __shfl_xor_sync(0xffffffffu, m, o));
    if (lane == 0) atomicMax(&g_maxbox, m);

    bool valid = s > 0.25f;
    bool act = valid && (x2 > x1) && (y2 > y1);
    u32 vb = __ballot_sync(0xffffffffu, valid);
    u32 ab = __ballot_sync(0xffffffffu, act);
    if (vb) {
        int leader = __ffs(vb) - 1;
        int base = 0;
        if (lane == leader) {
            base = atomicAdd(&g_cnt, __popc(vb));
            if (ab) atomicAdd(&g_cnt_a, __popc(ab));
        }
        base = __shfl_sync(0xffffffffu, base, leader);
        if (valid) {
            int slot = base + __popc(vb & ((1u << lane) - 1u));
            g_keys[slot] = ((u64)(~fmono(s)) << 32) | ((u32)i << 1) | (act ? 1u : 0u);
        }
    }
    for (int k = i; k < N*6; k += N) out[k] = 0.0f;   // zero full output
}

// O(n^2) rank sort: 32 i per block, j-loop split 8 ways -> ~103 active blocks.
// Passive boxes (zero area) never interact -> emitted directly here.
__global__ __launch_bounds__(256) void k_rank(float* __restrict__ out) {
    __shared__ u64 sk[2048];
    int cnt = g_cnt;
    if (blockIdx.x * 32 >= cnt) return;
    int tid = threadIdx.x;
    int i = blockIdx.x * 32 + (tid >> 3);
    int part = tid & 7;

    u64 ki = (i < cnt) ? g_keys[i] : ~0ull;
    int rank_all = 0, rank_act = 0;

    for (int base = 0; base < cnt; base += 2048) {
        int lim = min(2048, cnt - base);
        __syncthreads();
        for (int t = tid; t < lim; t += 256) sk[t] = g_keys[base + t];
        __syncthreads();
        for (int j = part; j < lim; j += 8) {
            u64 kj = sk[j];
            int lt = kj < ki;                      // full-u64 compare, no masking
            rank_all += lt;
            rank_act += lt & (int)(kj & 1ull);
        }
    }
    #pragma unroll
    for (int o = 1; o < 8; o <<= 1) {
        rank_all += __shfl_xor_sync(0xffffffffu, rank_all, o);
        rank_act += __shfl_xor_sync(0xffffffffu, rank_act, o);
    }

    if (part == 0 && i < cnt) {
        int o = (int)((ki >> 1) & 0x1FFFull);
        bool act = (ki & 1ull) != 0ull;
        float x1 = g_x1[o], y1 = g_y1[o], x2 = g_x2[o], y2 = g_y2[o], s = g_sc[o];
        if (act) {
            int r = rank_act;
            g_sx1[r]=x1; g_sy1[r]=y1; g_sx2[r]=x2; g_sy2[r]=y2;
            g_ssc[r]=s;  g_sar[r]=(x2-x1)*(y2-y1);
            g_apos[r]=rank_all;
        } else {
            float f = (g_maxbox <= 0xBF800000u) ? 1.0f : (1.0f / 416.0f);
            float* o6 = out + rank_all * 6;
            o6[0]=x1*f; o6[1]=y1*f; o6[2]=x2*f; o6[3]=y2*f; o6[4]=s; o6[5]=0.0f;
        }
    }
}

// pairwise IoU bitmask among actives: grid-stride over actual upper-triangle tiles
__global__ __launch_bounds__(256) void k_mask() {
    int cnt = g_cnt_a;
    if (cnt == 0) return;
    int W = (cnt + 63) >> 6;
    int itiles = (cnt + 15) >> 4;
    int wtiles = (W + 15) >> 4;
    int ntiles = itiles * wtiles;

    __shared__ float jx1[1040], jy1[1040], jx2[1040], jy2[1040], jar[1040];
    int tid = threadIdx.x;

    for (int t = blockIdx.x; t < ntiles; t += gridDim.x) {
        int i0 = (t / wtiles) * 16;
        int w0 = (t % wtiles) * 16;
        if ((w0 + 16) * 64 <= i0) continue;   // fully below diagonal (uniform per block)

        __syncthreads();                       // smem reuse guard
        for (int tt = tid; tt < 1024; tt += 256) {
            int j = w0 * 64 + tt;
            int jm = (tt >> 6) * 65 + (tt & 63);   // +1 pad per 64 -> conflict-free
            bool ok = j < cnt;
            jx1[jm] = ok ? g_sx1[j] :  3.4e38f;
            jy1[jm] = ok ? g_sy1[j] :  3.4e38f;
            jx2[jm] = ok ? g_sx2[j] : -3.4e38f;
            jy2[jm] = ok ? g_sy2[j] : -3.4e38f;
            jar[jm] = ok ? g_sar[j] : 0.0f;
        }
        __syncthreads();

        int r  = tid >> 4;          // row within tile
        int wl = tid & 15;          // word within tile
        int i = i0 + r;
        int w = w0 + wl;
        if (i < cnt && w < W) {
            float ix1 = g_sx1[i], iy1 = g_sy1[i], ix2 = g_sx2[i], iy2 = g_sy2[i], iar = g_sar[i];
            int base = wl * 65;
            u64 bits = 0;
            #pragma unroll 8
            for (int jj = 0; jj < 64; jj++) {
                float bx1 = jx1[base + jj], by1 = jy1[base + jj];
                float bx2 = jx2[base + jj], by2 = jy2[base + jj], ba = jar[base + jj];
                float xx1 = fmaxf(ix1, bx1), yy1 = fmaxf(iy1, by1);
                float xx2 = fminf(ix2, bx2), yy2 = fminf(iy2, by2);
                float dx = fmaxf(xx2 - xx1, 0.0f), dy = fmaxf(yy2 - yy1, 0.0f);
                float inter = dx * dy;
                float uni = iar + ba - inter;
                bool pred = (inter > 0.45f * uni) && (uni > 0.0f);
                bits |= ((u64)pred) << jj;
            }
            g_mask[(size_t)i * NW + w] = bits;
        }
    }
}

// minimal-barrier greedy scan: 128 threads stage the live mask into smem,
// ONE __syncthreads, then warp 0 runs the entire chunk loop alone:
// ballot fixed-point resolve + per-lane-owned apply (plain smem stores,
// no atomics, no block barriers) + emit. __syncwarp only.
__global__ __launch_bounds__(128) void k_scan(float* __restrict__ out) {
    extern __shared__ u64 smask[];           // staged mask: smask[r*W + w]
    __shared__ u64 s_remv[NW];
    int tid = threadIdx.x;
    int cnt = g_cnt_a;
    int W = (cnt + 63) >> 6;
    float f = (g_maxbox <= 0xBF800000u) ? 1.0f : (1.0f / 416.0f);

    bool fits = ((long long)cnt * W) <= SCAN_SMEM_WORDS;
    const u64* mptr = fits ? smask : g_mask;
    int stride = fits ? W : NW;

    if (fits) {
        // 4 threads per row, division-free, coalesced-ish 32B segments
        for (int r = tid >> 2; r < cnt; r += 32) {
            for (int w = tid & 3; w < W; w += 4)
                smask[r * W + w] = g_mask[(size_t)r * NW + w];
        }
    }
    for (int w = tid; w < NW; w += 128) s_remv[w] = 0ull;
    __syncthreads();                          // the ONLY block barrier
    if (tid >= 32) return;                    // warp 0 continues alone

    int l = tid;
    for (int c = 0; c < W; c++) {
        // ---- warp-parallel fixed-point resolve of chunk c ----
        u64 sup = s_remv[c];
        int lim = cnt - c * 64;
        if (lim < 64) sup |= ~((1ull << lim) - 1ull);   // tail rows = suppressed
        int r_lo = c * 64 + l, r_hi = r_lo + 32;
        u64 d_lo = (r_lo < cnt) ? mptr[(size_t)r_lo * stride + c] : 0ull;
        u64 d_hi = (r_hi < cnt) ? mptr[(size_t)r_hi * stride + c] : 0ull;
        u32 cand_lo = (u32)((sup >> l) & 1ull) ^ 1u;
        u32 cand_hi = (u32)((sup >> (l + 32)) & 1ull) ^ 1u;
        u64 below_lo = (1ull << l) - 1ull;
        u64 below_hi = (1ull << (l + 32)) - 1ull;

        u32 kl = __ballot_sync(0xffffffffu, cand_lo);
        u32 kh = __ballot_sync(0xffffffffu, cand_hi);
        while (true) {
            u64 kept = (u64)kl | ((u64)kh << 32);
            u32 nl = __ballot_sync(0xffffffffu,
                    cand_lo && ((d_lo & kept & below_lo) == 0ull));
            kept = (u64)nl | ((u64)kh << 32);            // Gauss-Seidel for hi half
            u32 nh = __ballot_sync(0xffffffffu,
                    cand_hi && ((d_hi & kept & below_hi) == 0ull));
            bool stable = (nl == kl) && (nh == kh);
            kl = nl; kh = nh;
            if (stable) break;                           // fixed point == greedy
        }
        u64 kb = (u64)kl | ((u64)kh << 32);              // known by all lanes

        // ---- emit kept rows (lane owns rows r_lo, r_hi); fire-and-forget ----
        if (r_lo < cnt && ((kb >> l) & 1ull)) {
            float* o = out + g_apos[r_lo] * 6;
            *(float2*)(o)     = make_float2(g_sx1[r_lo] * f, g_sy1[r_lo] * f);
            *(float2*)(o + 2) = make_float2(g_sx2[r_lo] * f, g_sy2[r_lo] * f);
            *(float2*)(o + 4) = make_float2(g_ssc[r_lo], 0.0f);
        }
        if (r_hi < cnt && ((kb >> (l + 32)) & 1ull)) {
            float* o = out + g_apos[r_hi] * 6;
            *(float2*)(o)     = make_float2(g_sx1[r_hi] * f, g_sy1[r_hi] * f);
            *(float2*)(o + 2) = make_float2(g_sx2[r_hi] * f, g_sy2[r_hi] * f);
            *(float2*)(o + 4) = make_float2(g_ssc[r_hi], 0.0f);
        }

        // ---- apply: lane owns future word w (one writer per word, no races) ----
        size_t base = (size_t)c * 64;
        for (int w = c + 1 + l; w < W; w += 32) {
            u64 acc = s_remv[w];
            #pragma unroll 8
            for (int b = 0; b < 64; b++)
                acc |= mptr[(base + b) * stride + w] & (0ull - ((kb >> b) & 1ull));
            s_remv[w] = acc;
        }
        __syncwarp();                                    // smem visibility in-warp
    }

    // reset counters for the next graph replay
    if (l == 0) { g_cnt = 0; g_cnt_a = 0; g_maxbox = 0u; }
}

extern "C" void kernel_launch(void* const* d_in, const int* in_sizes, int n_in,
                              void* d_out, int out_size) {
    const float* preds = (const float*)d_in[0];
    float* out = (float*)d_out;

    cudaFuncSetAttribute(k_scan, cudaFuncAttributeMaxDynamicSharedMemorySize,
                         SCAN_SMEM_WORDS * sizeof(u64));

    k_prep<<<N / 256, 256>>>(preds, out);
    k_rank<<<256, 256>>>(out);          // 32 i per block; excess blocks exit
    k_mask<<<128, 256>>>();
    k_scan<<<1, 128, SCAN_SMEM_WORDS * sizeof(u64)>>>(out);
}

// round 11
// speedup vs baseline: 1.5783x; 1.5783x over previous
#include <cuda_runtime.h>
#include <cstdint>

#define N 8192
#define NW 128          // max 64-bit words per active mask row (N/64)
#define SCAN_SMEM_WORDS 19456   // 152 KB dynamic smem budget for staged mask
typedef unsigned long long u64;
typedef unsigned int u32;

// ---------------- device globals (zero-initialized at module load) ----------------
__device__ u32 g_maxbox;
__device__ int g_cnt;      // valid boxes (score > 0.25)
__device__ int g_cnt_a;    // active valid boxes (positive area)
__device__ float g_x1[N], g_y1[N], g_x2[N], g_y2[N], g_sc[N];
__device__ u64 g_keys[N];  // (~mono(score))<<32 | idx<<1 | act   -- full-u64 comparable
__device__ float g_sx1[N], g_sy1[N], g_sx2[N], g_sy2[N], g_ssc[N], g_sar[N]; // sorted actives
__device__ int g_apos[N];  // sorted-active rank -> overall sorted position (output row)
__device__ u64 g_mask[N * NW];   // suppression bitmask among actives (full rows)

__device__ __forceinline__ u32 fmono(float f) {
    u32 u = __float_as_uint(f);
    return (u & 0x80000000u) ? ~u : (u | 0x80000000u);
}

// decode boxes, coord max, warp-aggregated compaction of valid keys, zero output
__global__ void k_prep(const float* __restrict__ p, float* __restrict__ out) {
    int i = blockIdx.x * blockDim.x + threadIdx.x;   // grid covers exactly N
    float cx = p[i], cy = p[N + i], pw = p[2*N + i], ph = p[3*N + i], s = p[4*N + i];
    float x1 = cx - pw*0.5f, y1 = cy - ph*0.5f, x2 = cx + pw*0.5f, y2 = cy + ph*0.5f;
    g_x1[i]=x1; g_y1[i]=y1; g_x2[i]=x2; g_y2[i]=y2; g_sc[i]=s;

    int lane = threadIdx.x & 31;
    u32 m = fmono(fmaxf(fmaxf(x1,x2), fmaxf(y1,y2)));
    #pragma unroll
    for (int o = 16; o; o >>= 1) m = max(m, __shfl_xor_sync(0xffffffffu, m, o));
    if (lane == 0) atomicMax(&g_maxbox, m);

    bool valid = s > 0.25f;
    bool act = valid && (x2 > x1) && (y2 > y1);
    u32 vb = __ballot_sync(0xffffffffu, valid);
    u32 ab = __ballot_sync(0xffffffffu, act);
    if (vb) {
        int leader = __ffs(vb) - 1;
        int base = 0;
        if (lane == leader) {
            base = atomicAdd(&g_cnt, __popc(vb));
            if (ab) atomicAdd(&g_cnt_a, __popc(ab));
        }
        base = __shfl_sync(0xffffffffu, base, leader);
        if (valid) {
            int slot = base + __popc(vb & ((1u << lane) - 1u));
            g_keys[slot] = ((u64)(~fmono(s)) << 32) | ((u32)i << 1) | (act ? 1u : 0u);
        }
    }
    for (int k = i; k < N*6; k += N) out[k] = 0.0f;   // zero full output
}

// O(n^2) rank sort: 32 i per block, j-loop split 8 ways -> ~103 active blocks.
// Passive boxes (zero area) never interact -> emitted directly here.
__global__ __launch_bounds__(256) void k_rank(float* __restrict__ out) {
    __shared__ u64 sk[2048];
    int cnt = g_cnt;
    if (blockIdx.x * 32 >= cnt) return;
    int tid = threadIdx.x;
    int i = blockIdx.x * 32 + (tid >> 3);
    int part = tid & 7;

    u64 ki = (i < cnt) ? g_keys[i] : ~0ull;
    int rank_all = 0, rank_act = 0;

    for (int base = 0; base < cnt; base += 2048) {
        int lim = min(2048, cnt - base);
        __syncthreads();
        for (int t = tid; t < lim; t += 256) sk[t] = g_keys[base + t];
        __syncthreads();
        for (int j = part; j < lim; j += 8) {
            u64 kj = sk[j];
            int lt = kj < ki;                      // full-u64 compare, no masking
            rank_all += lt;
            rank_act += lt & (int)(kj & 1ull);
        }
    }
    #pragma unroll
    for (int o = 1; o < 8; o <<= 1) {
        rank_all += __shfl_xor_sync(0xffffffffu, rank_all, o);
        rank_act += __shfl_xor_sync(0xffffffffu, rank_act, o);
    }

    if (part == 0 && i < cnt) {
        int o = (int)((ki >> 1) & 0x1FFFull);
        bool act = (ki & 1ull) != 0ull;
        float x1 = g_x1[o], y1 = g_y1[o], x2 = g_x2[o], y2 = g_y2[o], s = g_sc[o];
        if (act) {
            int r = rank_act;
            g_sx1[r]=x1; g_sy1[r]=y1; g_sx2[r]=x2; g_sy2[r]=y2;
            g_ssc[r]=s;  g_sar[r]=(x2-x1)*(y2-y1);
            g_apos[r]=rank_all;
        } else {
            float f = (g_maxbox <= 0xBF800000u) ? 1.0f : (1.0f / 416.0f);
            float* o6 = out + rank_all * 6;
            o6[0]=x1*f; o6[1]=y1*f; o6[2]=x2*f; o6[3]=y2*f; o6[4]=s; o6[5]=0.0f;
        }
    }
}

// pairwise IoU bitmask among actives: FULL rows (below-diagonal words included,
// needed by the global fixed-point scan). Grid-stride over all tiles.
__global__ __launch_bounds__(256) void k_mask() {
    int cnt = g_cnt_a;
    if (cnt == 0) return;
    int W = (cnt + 63) >> 6;
    int itiles = (cnt + 15) >> 4;
    int wtiles = (W + 15) >> 4;
    int ntiles = itiles * wtiles;

    __shared__ float jx1[1040], jy1[1040], jx2[1040], jy2[1040], jar[1040];
    int tid = threadIdx.x;

    for (int t = blockIdx.x; t < ntiles; t += gridDim.x) {
        int i0 = (t / wtiles) * 16;
        int w0 = (t % wtiles) * 16;

        __syncthreads();                       // smem reuse guard
        for (int tt = tid; tt < 1024; tt += 256) {
            int j = w0 * 64 + tt;
            int jm = (tt >> 6) * 65 + (tt & 63);   // +1 pad per 64 -> conflict-free
            bool ok = j < cnt;
            jx1[jm] = ok ? g_sx1[j] :  3.4e38f;
            jy1[jm] = ok ? g_sy1[j] :  3.4e38f;
            jx2[jm] = ok ? g_sx2[j] : -3.4e38f;
            jy2[jm] = ok ? g_sy2[j] : -3.4e38f;
            jar[jm] = ok ? g_sar[j] : 0.0f;
        }
        __syncthreads();

        int r  = tid >> 4;          // row within tile
        int wl = tid & 15;          // word within tile
        int i = i0 + r;
        int w = w0 + wl;
        if (i < cnt && w < W) {
            float ix1 = g_sx1[i], iy1 = g_sy1[i], ix2 = g_sx2[i], iy2 = g_sy2[i], iar = g_sar[i];
            int base = wl * 65;
            u64 bits = 0;
            #pragma unroll 8
            for (int jj = 0; jj < 64; jj++) {
                float bx1 = jx1[base + jj], by1 = jy1[base + jj];
                float bx2 = jx2[base + jj], by2 = jy2[base + jj], ba = jar[base + jj];
                float xx1 = fmaxf(ix1, bx1), yy1 = fmaxf(iy1, by1);
                float xx2 = fminf(ix2, bx2), yy2 = fminf(iy2, by2);
                float dx = fmaxf(xx2 - xx1, 0.0f), dy = fmaxf(yy2 - yy1, 0.0f);
                float inter = dx * dy;
                float uni = iar + ba - inter;
                bool pred = (inter > 0.45f * uni) && (uni > 0.0f);
                bits |= ((u64)pred) << jj;
            }
            g_mask[(size_t)i * NW + w] = bits;
        }
    }
}

// GLOBAL fixed-point greedy scan: no serial chunk loop.
// Iterate keep_j = (row_j & kept & below_j)==0 over ALL rows in parallel
// until stable; stable => unique fixed point == exact greedy NMS result.
__global__ __launch_bounds__(256) void k_scan(float* __restrict__ out) {
    extern __shared__ u64 smask[];           // staged mask: smask[r*W + w]
    __shared__ u64 s_kept[NW];
    __shared__ unsigned char s_flag[NW * 64];
    __shared__ int s_changed;
    int tid = threadIdx.x;
    int cnt = g_cnt_a;
    int W = (cnt + 63) >> 6;
    float f = (g_maxbox <= 0xBF800000u) ? 1.0f : (1.0f / 416.0f);

    if (cnt > 0) {
        bool fits = ((long long)cnt * W) <= SCAN_SMEM_WORDS;
        const u64* mptr = fits ? smask : g_mask;
        int stride = fits ? W : NW;

        if (fits) {
            for (int r = tid >> 2; r < cnt; r += 64)          // 4 threads per row
                for (int w = tid & 3; w < W; w += 4)
                    smask[r * W + w] = g_mask[(size_t)r * NW + w];
        }
        // init kept = all candidates (tail-masked), padded flags = 0
        for (int w = tid; w < W; w += 256) {
            int lim = cnt - w * 64;
            s_kept[w] = (lim >= 64) ? ~0ull : ((1ull << lim) - 1ull);
        }
        for (int r = cnt + tid; r < W * 64; r += 256) s_flag[r] = 0;
        __syncthreads();

        while (true) {
            if (tid == 0) s_changed = 0;
            // ---- compute phase: keep flag per row ----
            for (int r = tid; r < cnt; r += 256) {
                int wj = r >> 6;
                const u64* row = mptr + (size_t)r * stride;
                u64 acc = row[wj] & s_kept[wj] & ((1ull << (r & 63)) - 1ull);
                for (int w = 0; w < wj; w++) acc |= row[w] & s_kept[w];
                s_flag[r] = (acc == 0ull);
            }
            __syncthreads();
            // ---- pack phase: 8 warps ballot-pack words, detect change ----
            int wid = tid >> 5, lane = tid & 31;
            for (int w = wid; w < W; w += 8) {
                u32 lo = __ballot_sync(0xffffffffu, s_flag[w * 64 + lane] != 0);
                u32 hi = __ballot_sync(0xffffffffu, s_flag[w * 64 + 32 + lane] != 0);
                if (lane == 0) {
                    u64 nw_ = (u64)lo | ((u64)hi << 32);
                    if (nw_ != s_kept[w]) { s_kept[w] = nw_; s_changed = 1; }
                }
            }
            __syncthreads();
            int done = (s_changed == 0);
            __syncthreads();                   // protect s_changed reset next iter
            if (done) break;                   // stable == fixed point == greedy
        }

        // ---- emit kept rows ----
        for (int r = tid; r < cnt; r += 256) {
            if ((s_kept[r >> 6] >> (r & 63)) & 1ull) {
                float* o = out + g_apos[r] * 6;
                *(float2*)(o)     = make_float2(g_sx1[r] * f, g_sy1[r] * f);
                *(float2*)(o + 2) = make_float2(g_sx2[r] * f, g_sy2[r] * f);
                *(float2*)(o + 4) = make_float2(g_ssc[r], 0.0f);
            }
        }
    }

    // reset counters for the next graph replay
    if (tid == 0) { g_cnt = 0; g_cnt_a = 0; g_maxbox = 0u; }
}

extern "C" void kernel_launch(void* const* d_in, const int* in_sizes, int n_in,
                              void* d_out, int out_size) {
    const float* preds = (const float*)d_in[0];
    float* out = (float*)d_out;

    cudaFuncSetAttribute(k_scan, cudaFuncAttributeMaxDynamicSharedMemorySize,
                         SCAN_SMEM_WORDS * sizeof(u64));

    k_prep<<<N / 256, 256>>>(preds, out);
    k_rank<<<256, 256>>>(out);          // 32 i per block; excess blocks exit
    k_mask<<<128, 256>>>();
    k_scan<<<1, 256, SCAN_SMEM_WORDS * sizeof(u64)>>>(out);
}

// round 12
// speedup vs baseline: 2.2459x; 1.4229x over previous
#include <cuda_runtime.h>
#include <cstdint>

#define N 8192
#define NW 128          // max 64-bit words per active mask row (N/64)
#define MAXR 1024       // register fixed-point handles cnt_a <= MAXR
#define MAXW 16         // and W <= MAXW
typedef unsigned long long u64;
typedef unsigned int u32;

// ---------------- device globals (zero-initialized at module load) ----------------
__device__ u32 g_maxbox;
__device__ int g_cnt;      // valid boxes (score > 0.25)
__device__ int g_cnt_a;    // active valid boxes (positive area)
__device__ float g_x1[N], g_y1[N], g_x2[N], g_y2[N], g_sc[N];
__device__ u64 g_keys[N];  // (~mono(score))<<32 | idx<<1 | act   -- full-u64 comparable
__device__ float g_sx1[N], g_sy1[N], g_sx2[N], g_sy2[N], g_ssc[N], g_sar[N]; // sorted actives
__device__ int g_apos[N];  // sorted-active rank -> overall sorted position (output row)
__device__ u64 g_mask[N * NW];   // suppression bitmask among actives (full rows)

__device__ __forceinline__ u32 fmono(float f) {
    u32 u = __float_as_uint(f);
    return (u & 0x80000000u) ? ~u : (u | 0x80000000u);
}

// decode boxes, coord max, warp-aggregated compaction of valid keys, zero output
__global__ void k_prep(const float* __restrict__ p, float* __restrict__ out) {
    int i = blockIdx.x * blockDim.x + threadIdx.x;   // grid covers exactly N
    float cx = p[i], cy = p[N + i], pw = p[2*N + i], ph = p[3*N + i], s = p[4*N + i];
    float x1 = cx - pw*0.5f, y1 = cy - ph*0.5f, x2 = cx + pw*0.5f, y2 = cy + ph*0.5f;
    g_x1[i]=x1; g_y1[i]=y1; g_x2[i]=x2; g_y2[i]=y2; g_sc[i]=s;

    int lane = threadIdx.x & 31;
    u32 m = fmono(fmaxf(fmaxf(x1,x2), fmaxf(y1,y2)));
    #pragma unroll
    for (int o = 16; o; o >>= 1) m = max(m, __shfl_xor_sync(0xffffffffu, m, o));
    if (lane == 0) atomicMax(&g_maxbox, m);

    bool valid = s > 0.25f;
    bool act = valid && (x2 > x1) && (y2 > y1);
    u32 vb = __ballot_sync(0xffffffffu, valid);
    u32 ab = __ballot_sync(0xffffffffu, act);
    if (vb) {
        int leader = __ffs(vb) - 1;
        int base = 0;
        if (lane == leader) {
            base = atomicAdd(&g_cnt, __popc(vb));
            if (ab) atomicAdd(&g_cnt_a, __popc(ab));
        }
        base = __shfl_sync(0xffffffffu, base, leader);
        if (valid) {
            int slot = base + __popc(vb & ((1u << lane) - 1u));
            g_keys[slot] = ((u64)(~fmono(s)) << 32) | ((u32)i << 1) | (act ? 1u : 0u);
        }
    }
    for (int k = i; k < N*6; k += N) out[k] = 0.0f;   // zero full output
}

// O(n^2) rank sort: 32 i per block, j-loop split 8 ways -> ~103 active blocks.
// Passive boxes (zero area) never interact -> emitted directly here.
__global__ __launch_bounds__(256) void k_rank(float* __restrict__ out) {
    __shared__ u64 sk[2048];
    int cnt = g_cnt;
    if (blockIdx.x * 32 >= cnt) return;
    int tid = threadIdx.x;
    int i = blockIdx.x * 32 + (tid >> 3);
    int part = tid & 7;

    u64 ki = (i < cnt) ? g_keys[i] : ~0ull;
    int rank_all = 0, rank_act = 0;

    for (int base = 0; base < cnt; base += 2048) {
        int lim = min(2048, cnt - base);
        __syncthreads();
        for (int t = tid; t < lim; t += 256) sk[t] = g_keys[base + t];
        __syncthreads();
        for (int j = part; j < lim; j += 8) {
            u64 kj = sk[j];
            int lt = kj < ki;                      // full-u64 compare, no masking
            rank_all += lt;
            rank_act += lt & (int)(kj & 1ull);
        }
    }
    #pragma unroll
    for (int o = 1; o < 8; o <<= 1) {
        rank_all += __shfl_xor_sync(0xffffffffu, rank_all, o);
        rank_act += __shfl_xor_sync(0xffffffffu, rank_act, o);
    }

    if (part == 0 && i < cnt) {
        int o = (int)((ki >> 1) & 0x1FFFull);
        bool act = (ki & 1ull) != 0ull;
        float x1 = g_x1[o], y1 = g_y1[o], x2 = g_x2[o], y2 = g_y2[o], s = g_sc[o];
        if (act) {
            int r = rank_act;
            g_sx1[r]=x1; g_sy1[r]=y1; g_sx2[r]=x2; g_sy2[r]=y2;
            g_ssc[r]=s;  g_sar[r]=(x2-x1)*(y2-y1);
            g_apos[r]=rank_all;
        } else {
            float f = (g_maxbox <= 0xBF800000u) ? 1.0f : (1.0f / 416.0f);
            float* o6 = out + rank_all * 6;
            o6[0]=x1*f; o6[1]=y1*f; o6[2]=x2*f; o6[3]=y2*f; o6[4]=s; o6[5]=0.0f;
        }
    }
}

// pairwise IoU bitmask among actives. The fixed-point scan only reads words
// w <= r>>6 (lower triangle incl. diagonal), so tiles fully ABOVE the diagonal
// are skipped.
__global__ __launch_bounds__(256) void k_mask() {
    int cnt = g_cnt_a;
    if (cnt == 0) return;
    int W = (cnt + 63) >> 6;
    int itiles = (cnt + 15) >> 4;
    int wtiles = (W + 15) >> 4;
    int ntiles = itiles * wtiles;

    __shared__ float jx1[1040], jy1[1040], jx2[1040], jy2[1040], jar[1040];
    int tid = threadIdx.x;

    for (int t = blockIdx.x; t < ntiles; t += gridDim.x) {
        int i0 = (t / wtiles) * 16;
        int w0 = (t % wtiles) * 16;
        if (w0 > ((i0 + 15) >> 6)) continue;   // tile fully above diagonal: never read

        __syncthreads();                       // smem reuse guard
        for (int tt = tid; tt < 1024; tt += 256) {
            int j = w0 * 64 + tt;
            int jm = (tt >> 6) * 65 + (tt & 63);   // +1 pad per 64 -> conflict-free
            bool ok = j < cnt;
            jx1[jm] = ok ? g_sx1[j] :  3.4e38f;
            jy1[jm] = ok ? g_sy1[j] :  3.4e38f;
            jx2[jm] = ok ? g_sx2[j] : -3.4e38f;
            jy2[jm] = ok ? g_sy2[j] : -3.4e38f;
            jar[jm] = ok ? g_sar[j] : 0.0f;
        }
        __syncthreads();

        int r  = tid >> 4;          // row within tile
        int wl = tid & 15;          // word within tile
        int i = i0 + r;
        int w = w0 + wl;
        if (i < cnt && w < W) {
            float ix1 = g_sx1[i], iy1 = g_sy1[i], ix2 = g_sx2[i], iy2 = g_sy2[i], iar = g_sar[i];
            int base = wl * 65;
            u64 bits = 0;
            #pragma unroll 8
            for (int jj = 0; jj < 64; jj++) {
                float bx1 = jx1[base + jj], by1 = jy1[base + jj];
                float bx2 = jx2[base + jj], by2 = jy2[base + jj], ba = jar[base + jj];
                float xx1 = fmaxf(ix1, bx1), yy1 = fmaxf(iy1, by1);
                float xx2 = fminf(ix2, bx2), yy2 = fminf(iy2, by2);
                float dx = fmaxf(xx2 - xx1, 0.0f), dy = fmaxf(yy2 - yy1, 0.0f);
                float inter = dx * dy;
                float uni = iar + ba - inter;
                bool pred = (inter > 0.45f * uni) && (uni > 0.0f);
                bits |= ((u64)pred) << jj;
            }
            g_mask[(size_t)i * NW + w] = bits;
        }
    }
}

// REGISTER-RESIDENT global fixed-point greedy scan.
// 512 threads; thread t owns rows t and t+512 entirely in registers (words
// diagonal-masked at load). Each iteration: 16 broadcast LDS of kept words +
// register AND/OR, 2 ballots, 2 barriers. Stable => fixed point == greedy.
__global__ __launch_bounds__(512) void k_scan(float* __restrict__ out) {
    __shared__ u64 s_kept64[MAXW];            // rows' kept bits, u32-addressable
    __shared__ int s_chg[2];
    // fallback-path shared state (cnt > MAXR; never in practice, always correct)
    __shared__ u64 s_keptF[NW];
    __shared__ unsigned char s_flag[NW * 64];
    u32* s_kept32 = (u32*)s_kept64;

    int tid = threadIdx.x;
    int lane = tid & 31, warp = tid >> 5;
    int cnt = g_cnt_a;
    int W = (cnt + 63) >> 6;
    float f = (g_maxbox <= 0xBF800000u) ? 1.0f : (1.0f / 416.0f);

    if (cnt > 0 && cnt <= MAXR) {
        // ---- preload both rows into registers, masked to strict lower triangle ----
        int r1 = tid, r2 = tid + 512;
        int w1 = r1 >> 6, w2 = r2 >> 6;
        u64 row1[MAXW], row2[MAXW];
        #pragma unroll
        for (int w = 0; w < MAXW; w++) {
            u64 v1 = (r1 < cnt && w <= w1) ? g_mask[(size_t)r1 * NW + w] : 0ull;
            u64 v2 = (r2 < cnt && w <= w2) ? g_mask[(size_t)r2 * NW + w] : 0ull;
            if (w == w1) v1 &= (1ull << (r1 & 63)) - 1ull;
            if (w == w2) v2 &= (1ull << (r2 & 63)) - 1ull;
            row1[w] = v1; row2[w] = v2;
        }
        // init kept = all candidates; 32 u32 slots cover rows 0..1023
        auto candbits = [&](int base) -> u32 {
            if (cnt >= base + 32) return 0xffffffffu;
            if (cnt <= base) return 0u;
            return (1u << (cnt - base)) - 1u;
        };
        if (tid < 32) s_kept32[tid] = candbits(tid * 32);
        if (tid < 2) s_chg[tid] = 0;
        u32 old1 = candbits(warp * 32);          // ballots for my warp's rows
        u32 old2 = candbits(512 + warp * 32);
        __syncthreads();

        int it = 0;
        for (;;) {
            u64 a1 = 0, a2 = 0;
            #pragma unroll
            for (int w = 0; w < MAXW; w++) {
                u64 k = s_kept64[w];             // broadcast LDS
                a1 |= row1[w] & k;
                a2 |= row2[w] & k;
            }
            bool f1 = (r1 < cnt) && (a1 == 0ull);
            bool f2 = (r2 < cnt) && (a2 == 0ull);
            __syncthreads();                     // all reads of s_kept done
            u32 b1 = __ballot_sync(0xffffffffu, f1);
            u32 b2 = __ballot_sync(0xffffffffu, f2);
            bool chg = (b1 != old1) || (b2 != old2);
            old1 = b1; old2 = b2;
            if (lane == 0) {
                s_kept32[warp] = b1;             // rows 32*warp .. +31
                s_kept32[16 + warp] = b2;        // rows 512+32*warp .. +31
                if (chg) s_chg[it & 1] = 1;
            }
            if (tid == 0) s_chg[(it + 1) & 1] = 0;   // pre-reset next slot
            __syncthreads();
            if (!s_chg[it & 1]) break;           // stable == fixed point == greedy
            if (++it > MAXR) break;              // unreachable safety bound
        }

        // ---- emit: final ballots live in old1/old2 ----
        if (r1 < cnt && ((old1 >> lane) & 1u)) {
            float* o = out + g_apos[r1] * 6;
            *(float2*)(o)     = make_float2(g_sx1[r1] * f, g_sy1[r1] * f);
            *(float2*)(o + 2) = make_float2(g_sx2[r1] * f, g_sy2[r1] * f);
            *(float2*)(o + 4) = make_float2(g_ssc[r1], 0.0f);
        }
        if (r2 < cnt && ((old2 >> lane) & 1u)) {
            float* o = out + g_apos[r2] * 6;
            *(float2*)(o)     = make_float2(g_sx1[r2] * f, g_sy1[r2] * f);
            *(float2*)(o + 2) = make_float2(g_sx2[r2] * f, g_sy2[r2] * f);
            *(float2*)(o + 4) = make_float2(g_ssc[r2], 0.0f);
        }
    } else if (cnt > 0) {
        // ---- generic fallback: dynamic fixed point straight from g_mask ----
        for (int w = tid; w < W; w += 512) {
            int lim = cnt - w * 64;
            s_keptF[w] = (lim >= 64) ? ~0ull : ((1ull << lim) - 1ull);
        }
        for (int r = cnt + tid; r < W * 64; r += 512) s_flag[r] = 0;
        if (tid < 2) s_chg[tid] = 0;
        __syncthreads();
        int it = 0;
        for (;;) {
            for (int r = tid; r < cnt; r += 512) {
                int wj = r >> 6;
                const u64* row = g_mask + (size_t)r * NW;
                u64 acc = row[wj] & s_keptF[wj] & ((1ull << (r & 63)) - 1ull);
                for (int w = 0; w < wj; w++) acc |= row[w] & s_keptF[w];
                s_flag[r] = (acc == 0ull);
            }
            __syncthreads();
            for (int w = warp; w < W; w += 16) {
                u32 lo = __ballot_sync(0xffffffffu, s_flag[w * 64 + lane] != 0);
                u32 hi = __ballot_sync(0xffffffffu, s_flag[w * 64 + 32 + lane] != 0);
                if (lane == 0) {
                    u64 nw_ = (u64)lo | ((u64)hi << 32);
                    if (nw_ != s_keptF[w]) { s_keptF[w] = nw_; s_chg[it & 1] = 1; }
                }
            }
            if (tid == 0) s_chg[(it + 1) & 1] = 0;
            __syncthreads();
            if (!s_chg[it & 1]) break;
            if (++it > N) break;
        }
        for (int r = tid; r < cnt; r += 512) {
            if ((s_keptF[r >> 6] >> (r & 63)) & 1ull) {
                float* o = out + g_apos[r] * 6;
                *(float2*)(o)     = make_float2(g_sx1[r] * f, g_sy1[r] * f);
                *(float2*)(o + 2) = make_float2(g_sx2[r] * f, g_sy2[r] * f);
                *(float2*)(o + 4) = make_float2(g_ssc[r], 0.0f);
            }
        }
    }

    // reset counters for the next graph replay
    if (tid == 0) { g_cnt = 0; g_cnt_a = 0; g_maxbox = 0u; }
}

extern "C" void kernel_launch(void* const* d_in, const int* in_sizes, int n_in,
                              void* d_out, int out_size) {
    const float* preds = (const float*)d_in[0];
    float* out = (float*)d_out;

    k_prep<<<N / 256, 256>>>(preds, out);
    k_rank<<<256, 256>>>(out);          // 32 i per block; excess blocks exit
    k_mask<<<128, 256>>>();
    k_scan<<<1, 512>>>(out);
}

// round 13
// speedup vs baseline: 2.7599x; 1.2289x over previous
#include <cuda_runtime.h>
#include <cstdint>

#define N 8192
#define NW 128          // max 64-bit words per active mask row (N/64)
#define MAXR 1024       // register fixed-point handles cnt_a <= MAXR
#define MAXW 16         // and W <= MAXW
typedef unsigned long long u64;
typedef unsigned int u32;

// ---------------- device globals (zero-initialized at module load) ----------------
__device__ u32 g_maxbox;
__device__ int g_cnt;      // valid boxes (score > 0.25)
__device__ int g_cnt_a;    // active valid boxes (positive area)
__device__ float g_x1[N], g_y1[N], g_x2[N], g_y2[N], g_sc[N];
__device__ u64 g_keys[N];  // (~mono(score))<<32 | idx<<1 | act   -- full-u64 comparable
__device__ float g_sx1[N], g_sy1[N], g_sx2[N], g_sy2[N], g_ssc[N], g_sar[N]; // sorted actives
__device__ int g_apos[N];  // sorted-active rank -> overall sorted position (output row)
__device__ u64 g_mask[N * NW];   // suppression bitmask among actives (lower triangle)

__device__ __forceinline__ u32 fmono(float f) {
    u32 u = __float_as_uint(f);
    return (u & 0x80000000u) ? ~u : (u | 0x80000000u);
}

// decode boxes, coord max, warp-aggregated compaction of valid keys, zero output
__global__ void k_prep(const float* __restrict__ p, float* __restrict__ out) {
    int i = blockIdx.x * blockDim.x + threadIdx.x;   // grid covers exactly N
    float cx = p[i], cy = p[N + i], pw = p[2*N + i], ph = p[3*N + i], s = p[4*N + i];
    float x1 = cx - pw*0.5f, y1 = cy - ph*0.5f, x2 = cx + pw*0.5f, y2 = cy + ph*0.5f;
    g_x1[i]=x1; g_y1[i]=y1; g_x2[i]=x2; g_y2[i]=y2; g_sc[i]=s;

    int lane = threadIdx.x & 31;
    u32 m = fmono(fmaxf(fmaxf(x1,x2), fmaxf(y1,y2)));
    #pragma unroll
    for (int o = 16; o; o >>= 1) m = max(m, __shfl_xor_sync(0xffffffffu, m, o));
    if (lane == 0) atomicMax(&g_maxbox, m);

    bool valid = s > 0.25f;
    bool act = valid && (x2 > x1) && (y2 > y1);
    u32 vb = __ballot_sync(0xffffffffu, valid);
    u32 ab = __ballot_sync(0xffffffffu, act);
    if (vb) {
        int leader = __ffs(vb) - 1;
        int base = 0;
        if (lane == leader) {
            base = atomicAdd(&g_cnt, __popc(vb));
            if (ab) atomicAdd(&g_cnt_a, __popc(ab));
        }
        base = __shfl_sync(0xffffffffu, base, leader);
        if (valid) {
            int slot = base + __popc(vb & ((1u << lane) - 1u));
            g_keys[slot] = ((u64)(~fmono(s)) << 32) | ((u32)i << 1) | (act ? 1u : 0u);
        }
    }
    for (int k = i; k < N*6; k += N) out[k] = 0.0f;   // zero full output
}

// O(n^2) rank sort: 16 i per block, j-loop split 16 ways -> ~207 active blocks.
// Passive boxes (zero area) never interact -> emitted directly here.
__global__ __launch_bounds__(256) void k_rank(float* __restrict__ out) {
    __shared__ u64 sk[2048];
    int cnt = g_cnt;
    if (blockIdx.x * 16 >= cnt) return;
    int tid = threadIdx.x;
    int i = blockIdx.x * 16 + (tid >> 4);
    int part = tid & 15;

    u64 ki = (i < cnt) ? g_keys[i] : ~0ull;
    int rank_all = 0, rank_act = 0;

    for (int base = 0; base < cnt; base += 2048) {
        int lim = min(2048, cnt - base);
        __syncthreads();
        for (int t = tid; t < lim; t += 256) sk[t] = g_keys[base + t];
        __syncthreads();
        for (int j = part; j < lim; j += 16) {
            u64 kj = sk[j];
            int lt = kj < ki;                      // full-u64 compare
            rank_all += lt;
            rank_act += lt & (int)(kj & 1ull);
        }
    }
    #pragma unroll
    for (int o = 1; o < 16; o <<= 1) {             // sums within each 16-lane group
        rank_all += __shfl_xor_sync(0xffffffffu, rank_all, o);
        rank_act += __shfl_xor_sync(0xffffffffu, rank_act, o);
    }

    if (part == 0 && i < cnt) {
        int o = (int)((ki >> 1) & 0x1FFFull);
        bool act = (ki & 1ull) != 0ull;
        float x1 = g_x1[o], y1 = g_y1[o], x2 = g_x2[o], y2 = g_y2[o], s = g_sc[o];
        if (act) {
            int r = rank_act;
            g_sx1[r]=x1; g_sy1[r]=y1; g_sx2[r]=x2; g_sy2[r]=y2;
            g_ssc[r]=s;  g_sar[r]=(x2-x1)*(y2-y1);
            g_apos[r]=rank_all;
        } else {
            float f = (g_maxbox <= 0xBF800000u) ? 1.0f : (1.0f / 416.0f);
            float* o6 = out + rank_all * 6;
            o6[0]=x1*f; o6[1]=y1*f; o6[2]=x2*f; o6[3]=y2*f; o6[4]=s; o6[5]=0.0f;
        }
    }
}

// pairwise IoU bitmask, LOWER TRIANGLE ONLY (scan reads w <= r>>6).
// Tiles: 64 rows x 4 words; above-diagonal tiles skipped. 256 j boxes/tile in smem.
__global__ __launch_bounds__(256) void k_mask() {
    int cnt = g_cnt_a;
    if (cnt == 0) return;
    int C = (cnt + 63) >> 6;              // row chunks == words
    int wtiles = (C + 3) >> 2;
    int ntiles = C * wtiles;

    __shared__ float jx1[260], jy1[260], jx2[260], jy2[260], jar[260];
    int tid = threadIdx.x;

    for (int t = blockIdx.x; t < ntiles; t += gridDim.x) {
        int c  = t / wtiles;              // row chunk (rows c*64 .. c*64+63)
        int wt = t - c * wtiles;          // word tile (words wt*4 .. wt*4+3)
        if (wt * 4 > c) continue;         // fully above diagonal: never read

        __syncthreads();                  // smem reuse guard
        {
            int j = wt * 256 + tid;
            int jm = (tid >> 6) * 65 + (tid & 63);   // +1 pad per 64 -> conflict-free
            bool ok = j < cnt;
            jx1[jm] = ok ? g_sx1[j] :  3.4e38f;
            jy1[jm] = ok ? g_sy1[j] :  3.4e38f;
            jx2[jm] = ok ? g_sx2[j] : -3.4e38f;
            jy2[jm] = ok ? g_sy2[j] : -3.4e38f;
            jar[jm] = ok ? g_sar[j] : 0.0f;
        }
        __syncthreads();

        int i = c * 64 + (tid & 63);      // row
        int wl = tid >> 6;                // 0..3 word within tile
        int w = wt * 4 + wl;
        if (i < cnt && w < C && w <= (i >> 6)) {
            float ix1 = g_sx1[i], iy1 = g_sy1[i], ix2 = g_sx2[i], iy2 = g_sy2[i], iar = g_sar[i];
            int base = wl * 65;
            u64 bits = 0;
            #pragma unroll 8
            for (int jj = 0; jj < 64; jj++) {
                float bx1 = jx1[base + jj], by1 = jy1[base + jj];
                float bx2 = jx2[base + jj], by2 = jy2[base + jj], ba = jar[base + jj];
                float xx1 = fmaxf(ix1, bx1), yy1 = fmaxf(iy1, by1);
                float xx2 = fminf(ix2, bx2), yy2 = fminf(iy2, by2);
                float dx = fmaxf(xx2 - xx1, 0.0f), dy = fmaxf(yy2 - yy1, 0.0f);
                float inter = dx * dy;
                float uni = iar + ba - inter;
                bool pred = (inter > 0.45f * uni) && (uni > 0.0f);
                bits |= ((u64)pred) << jj;
            }
            g_mask[(size_t)i * NW + w] = bits;
        }
    }
}

// REGISTER-RESIDENT global fixed-point greedy scan, ONE barrier per iteration.
// 512 threads; thread t owns rows t (words<=8) and t+512 (words<=16) in regs,
// diagonal-masked, word loop bounded at each row's diagonal word.
// Double-buffered kept bits; stable => unique fixed point == exact greedy.
__global__ __launch_bounds__(512) void k_scan(float* __restrict__ out) {
    __shared__ u64 s_kept[2][MAXW];           // double buffer, u32-addressable
    __shared__ int s_chg[2];
    // fallback-path shared state (cnt > MAXR; never in practice, always correct)
    __shared__ u64 s_keptF[NW];
    __shared__ unsigned char s_flag[NW * 64];

    int tid = threadIdx.x;
    int lane = tid & 31, warp = tid >> 5;
    int cnt = g_cnt_a;
    int W = (cnt + 63) >> 6;
    float f = (g_maxbox <= 0xBF800000u) ? 1.0f : (1.0f / 416.0f);

    if (cnt > 0 && cnt <= MAXR) {
        int r1 = tid, r2 = tid + 512;
        int w1 = r1 >> 6, w2 = r2 >> 6;       // w1 in 0..7, w2 in 8..15
        u64 row1[8], row2[MAXW];
        #pragma unroll
        for (int w = 0; w < 8; w++) {
            u64 v = (r1 < cnt && w <= w1) ? g_mask[(size_t)r1 * NW + w] : 0ull;
            if (w == w1) v &= (1ull << (r1 & 63)) - 1ull;
            row1[w] = v;
        }
        #pragma unroll
        for (int w = 0; w < MAXW; w++) {
            u64 v = (r2 < cnt && w <= w2) ? g_mask[(size_t)r2 * NW + w] : 0ull;
            if (w == w2) v &= (1ull << (r2 & 63)) - 1ull;
            row2[w] = v;
        }
        auto candbits = [&](int base) -> u32 {
            if (cnt >= base + 32) return 0xffffffffu;
            if (cnt <= base) return 0u;
            return (1u << (cnt - base)) - 1u;
        };
        if (tid < 32) ((u32*)s_kept[0])[tid] = candbits(tid * 32);
        if (tid < 2) s_chg[tid] = 0;
        u32 old1 = candbits(warp * 32);       // my warp's rows: slots warp, 16+warp
        u32 old2 = candbits(512 + warp * 32);
        bool f1 = false, f2 = false;
        __syncthreads();

        int it = 0, p = 0;
        for (;;) {
            const u64* kp = s_kept[p];
            u64 a1 = 0, a2 = 0;
            #pragma unroll
            for (int w = 0; w < 8; w++) {     // bounded at diagonal word
                if (w > w1) break;
                a1 |= row1[w] & kp[w];
            }
            #pragma unroll
            for (int w = 0; w < MAXW; w++) {
                if (w > w2) break;
                a2 |= row2[w] & kp[w];
            }
            f1 = (r1 < cnt) && (a1 == 0ull);
            f2 = (r2 < cnt) && (a2 == 0ull);
            u32 b1 = __ballot_sync(0xffffffffu, f1);
            u32 b2 = __ballot_sync(0xffffffffu, f2);
            if (lane == 0) {
                ((u32*)s_kept[1 - p])[warp] = b1;
                ((u32*)s_kept[1 - p])[16 + warp] = b2;
                if (b1 != old1 || b2 != old2) s_chg[it & 1] = 1;
            }
            old1 = b1; old2 = b2;
            if (tid == 0) s_chg[(it + 1) & 1] = 0;   // pre-reset next slot
            __syncthreads();                          // the ONLY barrier
            if (!s_chg[it & 1]) break;               // stable == greedy
            p ^= 1;
            if (++it > MAXR) break;                  // unreachable safety bound
        }

        // ---- emit: final flags f1/f2 are the stable keep decisions ----
        if (f1) {
            float* o = out + g_apos[r1] * 6;
            *(float2*)(o)     = make_float2(g_sx1[r1] * f, g_sy1[r1] * f);
            *(float2*)(o + 2) = make_float2(g_sx2[r1] * f, g_sy2[r1] * f);
            *(float2*)(o + 4) = make_float2(g_ssc[r1], 0.0f);
        }
        if (f2) {
            float* o = out + g_apos[r2] * 6;
            *(float2*)(o)     = make_float2(g_sx1[r2] * f, g_sy1[r2] * f);
            *(float2*)(o + 2) = make_float2(g_sx2[r2] * f, g_sy2[r2] * f);
            *(float2*)(o + 4) = make_float2(g_ssc[r2], 0.0f);
        }
    } else if (cnt > 0) {
        // ---- generic fallback: dynamic fixed point straight from g_mask ----
        for (int w = tid; w < W; w += 512) {
            int lim = cnt - w * 64;
            s_keptF[w] = (lim >= 64) ? ~0ull : ((1ull << lim) - 1ull);
        }
        for (int r = cnt + tid; r < W * 64; r += 512) s_flag[r] = 0;
        if (tid < 2) s_chg[tid] = 0;
        __syncthreads();
        int it = 0;
        for (;;) {
            for (int r = tid; r < cnt; r += 512) {
                int wj = r >> 6;
                const u64* row = g_mask + (size_t)r * NW;
                u64 acc = row[wj] & s_keptF[wj] & ((1ull << (r & 63)) - 1ull);
                for (int w = 0; w < wj; w++) acc |= row[w] & s_keptF[w];
                s_flag[r] = (acc == 0ull);
            }
            __syncthreads();
            for (int w = warp; w < W; w += 16) {
                u32 lo = __ballot_sync(0xffffffffu, s_flag[w * 64 + lane] != 0);
                u32 hi = __ballot_sync(0xffffffffu, s_flag[w * 64 + 32 + lane] != 0);
                if (lane == 0) {
                    u64 nw_ = (u64)lo | ((u64)hi << 32);
                    if (nw_ != s_keptF[w]) { s_keptF[w] = nw_; s_chg[it & 1] = 1; }
                }
            }
            if (tid == 0) s_chg[(it + 1) & 1] = 0;
            __syncthreads();
            if (!s_chg[it & 1]) break;
            if (++it > N) break;
        }
        for (int r = tid; r < cnt; r += 512) {
            if ((s_keptF[r >> 6] >> (r & 63)) & 1ull) {
                float* o = out + g_apos[r] * 6;
                *(float2*)(o)     = make_float2(g_sx1[r] * f, g_sy1[r] * f);
                *(float2*)(o + 2) = make_float2(g_sx2[r] * f, g_sy2[r] * f);
                *(float2*)(o + 4) = make_float2(g_ssc[r], 0.0f);
            }
        }
    }

    // reset counters for the next graph replay
    if (tid == 0) { g_cnt = 0; g_cnt_a = 0; g_maxbox = 0u; }
}

extern "C" void kernel_launch(void* const* d_in, const int* in_sizes, int n_in,
                              void* d_out, int out_size) {
    const float* preds = (const float*)d_in[0];
    float* out = (float*)d_out;

    k_prep<<<N / 256, 256>>>(preds, out);
    k_rank<<<512, 256>>>(out);          // 16 i per block; excess blocks exit
    k_mask<<<64, 256>>>();
    k_scan<<<1, 512>>>(out);
}